// round 7
// baseline (speedup 1.0000x reference)
#include <cuda_runtime.h>
#include <cuda_bf16.h>
#include <cstdint>
#include <cstddef>

#define N_NODES 200000
#define C 128
#define S 6
#define EP 100000
#define EL 25000
#define CC 16384

typedef unsigned long long u64;
typedef unsigned int u32;

// ---- static device scratch ----
__device__ float g_F[(size_t)N_NODES * C];
__device__ float g_G[(size_t)N_NODES * C];
__device__ float g_T[(size_t)N_NODES * C];
__device__ __nv_bfloat16 g_Fhi[(size_t)N_NODES * C];
__device__ __nv_bfloat16 g_Flo[(size_t)N_NODES * C];
__device__ __nv_bfloat16 g_Xhi[(size_t)N_NODES * C];
__device__ __nv_bfloat16 g_Xlo[(size_t)N_NODES * C];
__device__ __nv_bfloat16 g_Whi[(size_t)67 * CC];
__device__ __nv_bfloat16 g_Wlo[(size_t)67 * CC];

// weight slots (transposed Wt[n][k], bf16 hi/lo)
// 0 in2 | 1 seg2 | 2 meta | 3..50 pre/suc per layer (12 each: pre s0..5, suc s0..5)
// 51..58 left/right per layer (2 each) | 59..62 ctr | 63..66 ctr2
#define OFF_IN2   0
#define OFF_SEG2  (1 * CC)
#define OFF_META  (2 * CC)
#define OFF_PS    (3 * CC)
#define OFF_LR    (51 * CC)
#define OFF_CTR   (59 * CC)
#define OFF_CTR2  (63 * CC)

// ---- helpers ----
__device__ __forceinline__ u32 cvta_sm(const void* p) {
    u32 a;
    asm("{ .reg .u64 t; cvta.to.shared.u64 t, %1; cvt.u32.u64 %0, t; }" : "=r"(a) : "l"(p));
    return a;
}
__device__ __forceinline__ void red4(float* p, float a, float b, float c, float d) {
    asm volatile("red.global.add.v4.f32 [%0], {%1,%2,%3,%4};"
                 :: "l"(p), "f"(a), "f"(b), "f"(c), "f"(d) : "memory");
}
__device__ __forceinline__ void red2(float* p, float a, float b) {
    asm volatile("red.global.add.v2.f32 [%0], {%1,%2};"
                 :: "l"(p), "f"(a), "f"(b) : "memory");
}
__device__ __forceinline__ u32 pack_bf2(float a, float b) {
    __nv_bfloat162 t = __floats2bfloat162_rn(a, b);
    return *(u32*)&t;
}
__device__ __forceinline__ void ldm4(u32* r, u32 addr) {
    asm volatile("ldmatrix.sync.aligned.m8n8.x4.shared.b16 {%0,%1,%2,%3}, [%4];"
                 : "=r"(r[0]), "=r"(r[1]), "=r"(r[2]), "=r"(r[3]) : "r"(addr));
}
__device__ __forceinline__ void mma_bf16(float* c, const u32* a, const u32* b) {
    asm volatile(
        "mma.sync.aligned.m16n8k16.row.col.f32.bf16.bf16.f32 "
        "{%0,%1,%2,%3}, {%4,%5,%6,%7}, {%8,%9}, {%0,%1,%2,%3};"
        : "+f"(c[0]), "+f"(c[1]), "+f"(c[2]), "+f"(c[3])
        : "r"(a[0]), "r"(a[1]), "r"(a[2]), "r"(a[3]), "r"(b[0]), "r"(b[1]));
}
__device__ __forceinline__ void cpa16(u32 dst, const void* src, u32 sz) {
    asm volatile("cp.async.cg.shared.global [%0], [%1], 16, %2;"
                 :: "r"(dst), "l"(src), "r"(sz) : "memory");
}
#define CP_COMMIT() asm volatile("cp.async.commit_group;" ::: "memory")

// 64B-row swizzle: chunk' = chunk ^ ((row>>1)&3)
__device__ __forceinline__ u32 swz(int r, int c) {
    return (u32)r * 64u + (u32)((c ^ ((r >> 1) & 3)) << 4);
}

#define MMAS(A, B) do {                                                        \
    _Pragma("unroll") for (int mi_ = 0; mi_ < 2; mi_++)                        \
        _Pragma("unroll") for (int ni_ = 0; ni_ < 4; ni_++) {                  \
            mma_bf16(acc[mi_][2 * ni_],     (A)[mi_], &(B)[ni_][0]);           \
            mma_bf16(acc[mi_][2 * ni_ + 1], (A)[mi_], &(B)[ni_][2]);           \
        }                                                                      \
} while (0)

// ================= dense bf16x3 GEMM (3-buffer pipeline) =================
#define MTB   8192
#define OFF_AH 0
#define OFF_AL (1 * MTB)
#define OFF_BH (2 * MTB)
#define OFF_BL (3 * MTB)
#define QSET  (4 * MTB)
#define SM_IDX (3 * QSET)
#define DSM   (SM_IDX + 1024)
#define LDC   132

__device__ __forceinline__ void stage_q_d(
    u32 smb, int q, int bi, int tid, int row0, int nrows,
    const __nv_bfloat16* Ahi, const __nv_bfloat16* Alo,
    const __nv_bfloat16* WH, const __nv_bfloat16* WL)
{
    u32 bbase = smb + (u32)bi * QSET;
    #pragma unroll
    for (int j = 0; j < 2; j++) {
        int id = tid + j * 256;
        int r = id >> 2, sg = id & 3;
        u32 doff = swz(r, sg);
        u32 asz = 16;
        int gr = row0 + r;
        if (gr >= nrows) { asz = 0; gr = 0; }
        size_t abyte = (size_t)gr * 256 + (size_t)q * 64 + (size_t)sg * 16;
        cpa16(bbase + OFF_AH + doff, (const char*)Ahi + abyte, asz);
        cpa16(bbase + OFF_AL + doff, (const char*)Alo + abyte, asz);
        size_t wbyte = (size_t)r * 256 + (size_t)q * 64 + (size_t)sg * 16;
        cpa16(bbase + OFF_BH + doff, (const char*)WH + wbyte, 16);
        cpa16(bbase + OFF_BL + doff, (const char*)WL + wbyte, 16);
    }
    CP_COMMIT();
}

// EPI: 0 store | 2 GN+add+relu+split | 3 extras+GN+relu+split | 4 GN only
template<int EPI>
__global__ __launch_bounds__(256, 2) void hmma_gemm(
    const __nv_bfloat16* __restrict__ Ahi, const __nv_bfloat16* __restrict__ Alo,
    const __nv_bfloat16* __restrict__ Whi, const __nv_bfloat16* __restrict__ Wlo,
    float* __restrict__ out,
    const float* __restrict__ gng, const float* __restrict__ gnb,
    const float* __restrict__ addb,
    __nv_bfloat16* __restrict__ fo_hi, __nv_bfloat16* __restrict__ fo_lo,
    int nrows,
    const float* __restrict__ turn, const float* __restrict__ control,
    const float* __restrict__ inter, const float* __restrict__ wext)
{
    extern __shared__ char dsm[];
    const int tid = threadIdx.x;
    const int wid = tid >> 5;
    const int lane = tid & 31;
    const int row0 = blockIdx.x * 128;
    const u32 smb = cvta_sm(dsm);

    const int wm = (wid & 3) * 32;
    const int wn = (wid >> 2) * 64;

    float acc[2][8][4];
    #pragma unroll
    for (int mi = 0; mi < 2; mi++)
        #pragma unroll
        for (int nj = 0; nj < 8; nj++)
            #pragma unroll
            for (int q = 0; q < 4; q++) acc[mi][nj][q] = 0.f;

    const int ra = wm + (lane & 15);
    const u32 xa = (u32)((ra >> 1) & 3);
    const int ca = lane >> 4;
    const int rb = wn + (lane & 7) + ((lane >> 4) & 1) * 8;
    const u32 xb = (u32)((rb >> 1) & 3);
    const int cb = (lane >> 3) & 1;

    stage_q_d(smb, 0, 0, tid, row0, nrows, Ahi, Alo, Whi, Wlo);
    stage_q_d(smb, 1, 1, tid, row0, nrows, Ahi, Alo, Whi, Wlo);
    stage_q_d(smb, 2, 2, tid, row0, nrows, Ahi, Alo, Whi, Wlo);

    #pragma unroll
    for (int q = 0; q < 4; q++) {
        if (q <= 1)      asm volatile("cp.async.wait_group 2;" ::: "memory");
        else if (q == 2) asm volatile("cp.async.wait_group 1;" ::: "memory");
        else             asm volatile("cp.async.wait_group 0;" ::: "memory");
        __syncthreads();

        const u32 qb = smb + (u32)(q % 3) * QSET;
        #pragma unroll
        for (int ks = 0; ks < 2; ks++) {
            const u32 ach = (u32)(ks * 2 + ca) ^ xa;
            const u32 bch = (u32)(ks * 2 + cb) ^ xb;
            const u32 aoff = (u32)ra * 64u + (ach << 4);
            u32 a0[2][4], a1[2][4], b0[4][4], b1[4][4];
            ldm4(a0[0], qb + OFF_AH + aoff);
            ldm4(a0[1], qb + OFF_AH + aoff + 16 * 64);
            #pragma unroll
            for (int ni = 0; ni < 4; ni++)
                ldm4(b0[ni], qb + OFF_BH + (u32)(rb + ni * 16) * 64u + (bch << 4));
            MMAS(a0, b0);
            ldm4(a1[0], qb + OFF_AL + aoff);
            ldm4(a1[1], qb + OFF_AL + aoff + 16 * 64);
            MMAS(a1, b0);
            #pragma unroll
            for (int ni = 0; ni < 4; ni++)
                ldm4(b1[ni], qb + OFF_BL + (u32)(rb + ni * 16) * 64u + (bch << 4));
            MMAS(a0, b1);
        }

        if (q == 0) {
            __syncthreads();
            stage_q_d(smb, 3, 0, tid, row0, nrows, Ahi, Alo, Whi, Wlo);
        }
    }

    // ---- accumulators -> smem C tile ----
    __syncthreads();
    float* Csm = (float*)dsm;
    #pragma unroll
    for (int mi = 0; mi < 2; mi++)
        #pragma unroll
        for (int nj = 0; nj < 8; nj++) {
            int r = wm + mi * 16 + (lane >> 2);
            int c = wn + nj * 8 + (lane & 3) * 2;
            float* p = Csm + (size_t)r * LDC + c;
            p[0] = acc[mi][nj][0];
            p[1] = acc[mi][nj][1];
            p[8 * LDC] = acc[mi][nj][2];
            p[8 * LDC + 1] = acc[mi][nj][3];
        }
    __syncthreads();

    float4 gv, bv;
    float4 we[4];
    if (EPI == 2 || EPI == 3 || EPI == 4) {
        gv = *(const float4*)(gng + lane * 4);
        bv = *(const float4*)(gnb + lane * 4);
    }
    if (EPI == 3) {
        #pragma unroll
        for (int j = 0; j < 4; j++)
            we[j] = *(const float4*)(wext + (size_t)j * C + lane * 4);
    }

    for (int i = 0; i < 16; i++) {
        int r = wid * 16 + i;
        int row = row0 + r;
        if (row >= nrows) continue;
        float4 v = *(float4*)(Csm + (size_t)r * LDC + lane * 4);

        if (EPI == 0) {
            *(float4*)(out + (size_t)row * C + lane * 4) = v;
            continue;
        }
        if (EPI == 3) {
            float t0 = turn[2 * row], t1 = turn[2 * row + 1];
            float cc0 = control[row], it = inter[row];
            v.x += t0 * we[0].x + t1 * we[1].x + cc0 * we[2].x + it * we[3].x;
            v.y += t0 * we[0].y + t1 * we[1].y + cc0 * we[2].y + it * we[3].y;
            v.z += t0 * we[0].z + t1 * we[1].z + cc0 * we[2].z + it * we[3].z;
            v.w += t0 * we[0].w + t1 * we[1].w + cc0 * we[2].w + it * we[3].w;
        }
        float s1 = v.x + v.y + v.z + v.w;
        float s2 = v.x * v.x + v.y * v.y + v.z * v.z + v.w * v.w;
        #pragma unroll
        for (int o = 16; o >= 1; o >>= 1) {
            s1 += __shfl_xor_sync(0xffffffffu, s1, o);
            s2 += __shfl_xor_sync(0xffffffffu, s2, o);
        }
        float mu = s1 * (1.f / 128.f);
        float var = s2 * (1.f / 128.f) - mu * mu;
        float rs = rsqrtf(var + 1e-5f);
        float v0 = (v.x - mu) * rs * gv.x + bv.x;
        float v1 = (v.y - mu) * rs * gv.y + bv.y;
        float v2 = (v.z - mu) * rs * gv.z + bv.z;
        float v3 = (v.w - mu) * rs * gv.w + bv.w;

        if (EPI == 4) {
            *(float4*)(out + (size_t)row * C + lane * 4) = make_float4(v0, v1, v2, v3);
            continue;
        }
        if (EPI == 2) {
            float4 rr = *(const float4*)(addb + (size_t)row * C + lane * 4);
            v0 += rr.x; v1 += rr.y; v2 += rr.z; v3 += rr.w;
        }
        v0 = fmaxf(v0, 0.f); v1 = fmaxf(v1, 0.f);
        v2 = fmaxf(v2, 0.f); v3 = fmaxf(v3, 0.f);
        *(float4*)(out + (size_t)row * C + lane * 4) = make_float4(v0, v1, v2, v3);
        __nv_bfloat16 h0 = __float2bfloat16(v0), h1 = __float2bfloat16(v1);
        __nv_bfloat16 h2 = __float2bfloat16(v2), h3 = __float2bfloat16(v3);
        __nv_bfloat162 hh0; hh0.x = h0; hh0.y = h1;
        __nv_bfloat162 hh1; hh1.x = h2; hh1.y = h3;
        uint2 H; H.x = *(u32*)&hh0; H.y = *(u32*)&hh1;
        uint2 L;
        L.x = pack_bf2(v0 - __bfloat162float(h0), v1 - __bfloat162float(h1));
        L.y = pack_bf2(v2 - __bfloat162float(h2), v3 - __bfloat162float(h3));
        *(uint2*)((char*)fo_hi + ((size_t)row * C + lane * 4) * 2) = H;
        *(uint2*)((char*)fo_lo + ((size_t)row * C + lane * 4) * 2) = L;
    }
}

// ================= edge GEMM: persistent B, multi-tile, direct RED ============
// smem: BH 4 quarters @0 (32KB) | BL @32768 (32KB) | A 2 bufs (AH+AL) @65536 (32KB)
//       idx @98304 (1KB)
#define E_BH  0
#define E_BL  32768
#define E_A   65536
#define E_IDX 98304
#define E_DSM 99328

__global__ __launch_bounds__(256, 2) void edge_gemm(
    const __nv_bfloat16* __restrict__ Ahi, const __nv_bfloat16* __restrict__ Alo,
    const __nv_bfloat16* __restrict__ Whi, const __nv_bfloat16* __restrict__ Wlo,
    float* __restrict__ T,
    const int* __restrict__ idxA, const int* __restrict__ idxB,
    int nh, long long istride, long long srcoff,
    int nedges, int tpc)
{
    extern __shared__ char dsm[];
    const int tid = threadIdx.x;
    const int wid = tid >> 5;
    const int lane = tid & 31;
    const u32 smb = cvta_sm(dsm);
    int* s_dst = (int*)(dsm + E_IDX);
    int* s_src = s_dst + 128;

    const int y = blockIdx.y;
    const int* dbase = ((y < nh) ? idxA : idxB) + (long long)(y % nh) * istride;
    const int* sbase = dbase + srcoff;
    const __nv_bfloat16* WH = Whi + (long long)y * CC;
    const __nv_bfloat16* WL = Wlo + (long long)y * CC;

    // stage persistent B (4 quarter blocks of 64B rows, swizzled)
    for (int v = tid; v < 2048; v += 256) {
        int q = v >> 9, rr = (v >> 2) & 127, sg = v & 3;
        u32 o = (u32)q * 8192u + swz(rr, sg);
        size_t gb = (size_t)rr * 256 + (size_t)q * 64 + (size_t)sg * 16;
        cpa16(smb + E_BH + o, (const char*)WH + gb, 16);
        cpa16(smb + E_BL + o, (const char*)WL + gb, 16);
    }
    CP_COMMIT();
    asm volatile("cp.async.wait_group 0;" ::: "memory");
    __syncthreads();

    const int wm = (wid & 3) * 32;
    const int wn = (wid >> 2) * 64;
    const int ra = wm + (lane & 15);
    const u32 xa = (u32)((ra >> 1) & 3);
    const int ca = lane >> 4;
    const int rb = wn + (lane & 7) + ((lane >> 4) & 1) * 8;
    const u32 xb = (u32)((rb >> 1) & 3);
    const int cb = (lane >> 3) & 1;

    const int ntiles = (nedges + 127) >> 7;
    int t0 = blockIdx.x * tpc;
    int t1 = t0 + tpc; if (t1 > ntiles) t1 = ntiles;

    for (int t = t0; t < t1; t++) {
        __syncthreads();
        if (tid < 128) {
            int e = t * 128 + tid;
            s_dst[tid] = (e < nedges) ? dbase[e] : -1;
            s_src[tid] = (e < nedges) ? sbase[e] : 0;
        }
        __syncthreads();

        float acc[2][8][4];
        #pragma unroll
        for (int mi = 0; mi < 2; mi++)
            #pragma unroll
            for (int nj = 0; nj < 8; nj++)
                #pragma unroll
                for (int q = 0; q < 4; q++) acc[mi][nj][q] = 0.f;

        // stage A quarters 0,1 into bufs 0,1
        #pragma unroll
        for (int qq = 0; qq < 2; qq++) {
            u32 bbase = smb + E_A + (u32)qq * 16384u;
            #pragma unroll
            for (int j = 0; j < 2; j++) {
                int id = tid + j * 256;
                int r = id >> 2, sg = id & 3;
                size_t abyte = (size_t)s_src[r] * 256 + (size_t)qq * 64 + (size_t)sg * 16;
                u32 doff = swz(r, sg);
                cpa16(bbase + doff, (const char*)Ahi + abyte, 16);
                cpa16(bbase + 8192u + doff, (const char*)Alo + abyte, 16);
            }
            CP_COMMIT();
        }

        #pragma unroll
        for (int q = 0; q < 4; q++) {
            if (q == 3) asm volatile("cp.async.wait_group 0;" ::: "memory");
            else        asm volatile("cp.async.wait_group 1;" ::: "memory");
            __syncthreads();

            const u32 ab = smb + E_A + (u32)(q & 1) * 16384u;
            const u32 bqh = smb + E_BH + (u32)q * 8192u;
            const u32 bql = smb + E_BL + (u32)q * 8192u;
            #pragma unroll
            for (int ks = 0; ks < 2; ks++) {
                const u32 ach = (u32)(ks * 2 + ca) ^ xa;
                const u32 bch = (u32)(ks * 2 + cb) ^ xb;
                const u32 aoff = (u32)ra * 64u + (ach << 4);
                u32 a0[2][4], a1[2][4], b0[4][4], b1[4][4];
                ldm4(a0[0], ab + aoff);
                ldm4(a0[1], ab + aoff + 16 * 64);
                #pragma unroll
                for (int ni = 0; ni < 4; ni++)
                    ldm4(b0[ni], bqh + (u32)(rb + ni * 16) * 64u + (bch << 4));
                MMAS(a0, b0);
                ldm4(a1[0], ab + 8192u + aoff);
                ldm4(a1[1], ab + 8192u + aoff + 16 * 64);
                MMAS(a1, b0);
                #pragma unroll
                for (int ni = 0; ni < 4; ni++)
                    ldm4(b1[ni], bql + (u32)(rb + ni * 16) * 64u + (bch << 4));
                MMAS(a0, b1);
            }

            if (q < 2) {
                __syncthreads();   // all warps done reading buf (q&1)
                u32 bbase = smb + E_A + (u32)(q & 1) * 16384u;
                int qq = q + 2;
                #pragma unroll
                for (int j = 0; j < 2; j++) {
                    int id = tid + j * 256;
                    int r = id >> 2, sg = id & 3;
                    size_t abyte = (size_t)s_src[r] * 256 + (size_t)qq * 64 + (size_t)sg * 16;
                    u32 doff = swz(r, sg);
                    cpa16(bbase + doff, (const char*)Ahi + abyte, 16);
                    cpa16(bbase + 8192u + doff, (const char*)Alo + abyte, 16);
                }
                CP_COMMIT();
            }
        }

        // direct RED scatter from fragments
        #pragma unroll
        for (int mi = 0; mi < 2; mi++) {
            int r0 = wm + mi * 16 + (lane >> 2);
            int d0 = s_dst[r0], d1 = s_dst[r0 + 8];
            #pragma unroll
            for (int nj = 0; nj < 8; nj++) {
                int cn = wn + nj * 8 + (lane & 3) * 2;
                if (d0 >= 0) red2(T + (size_t)d0 * C + cn, acc[mi][nj][0], acc[mi][nj][1]);
                if (d1 >= 0) red2(T + (size_t)d1 * C + cn, acc[mi][nj][2], acc[mi][nj][3]);
            }
        }
    }
}

// ================= fused prep kernel =================
#define PREP_COPY_B 1563
#define PREP_W_B    4288
#define PREP_IN_B   100000

__global__ void prep(
    const float* __restrict__ ctrs, const float* __restrict__ feats,
    const float* __restrict__ w_in1, const float* __restrict__ b_in1,
    const float* __restrict__ w_seg1, const float* __restrict__ b_seg1,
    const float* __restrict__ w_in2, const float* __restrict__ w_seg2,
    const float* __restrict__ w_meta,
    const float* __restrict__ ctr_w, const float* __restrict__ pre_w,
    const float* __restrict__ suc_w, const float* __restrict__ left_w,
    const float* __restrict__ right_w, const float* __restrict__ ctr2_w,
    __nv_bfloat16* __restrict__ whi, __nv_bfloat16* __restrict__ wlo,
    __nv_bfloat16* __restrict__ h1h, __nv_bfloat16* __restrict__ h1l,
    __nv_bfloat16* __restrict__ h2h, __nv_bfloat16* __restrict__ h2l,
    float* __restrict__ out_tail)
{
    int b = blockIdx.x;
    int tid = threadIdx.x;
    if (b < PREP_COPY_B) {
        int i = b * 256 + tid;
        if (i < N_NODES * 2) out_tail[i] = ctrs[i];
        return;
    }
    b -= PREP_COPY_B;
    if (b < PREP_W_B) {
        int idx = b * 256 + tid;
        int mat = idx >> 14;
        int rem = idx & 16383;
        int k = rem >> 7, n = rem & 127;
        const float* src;
        if      (mat == 0) src = w_in2 + rem;
        else if (mat == 1) src = w_seg2 + rem;
        else if (mat == 2) src = w_meta + rem;
        else if (mat < 51) {
            int m = mat - 3; int i = m / 12; int r = m % 12;
            src = (r < 6) ? pre_w + (size_t)(i * 6 + r) * CC + rem
                          : suc_w + (size_t)(i * 6 + r - 6) * CC + rem;
        } else if (mat < 59) {
            int m = mat - 51; int i = m >> 1;
            src = ((m & 1) ? right_w : left_w) + (size_t)i * CC + rem;
        } else if (mat < 63) src = ctr_w  + (size_t)(mat - 59) * CC + rem;
        else                 src = ctr2_w + (size_t)(mat - 63) * CC + rem;
        float x = *src;
        __nv_bfloat16 h = __float2bfloat16(x);
        size_t o = (size_t)mat * CC + (size_t)n * C + k;
        whi[o] = h;
        wlo[o] = __float2bfloat16(x - __bfloat162float(h));
        return;
    }
    b -= PREP_W_B;
    {
        int i = b * 256 + tid;
        int n = i >> 7, cc = i & 127;
        float x0 = ctrs[2 * n], x1 = ctrs[2 * n + 1];
        float a = fmaxf(x0 * w_in1[cc] + x1 * w_in1[C + cc] + b_in1[cc], 0.f);
        __nv_bfloat16 ah = __float2bfloat16(a);
        h1h[i] = ah;
        h1l[i] = __float2bfloat16(a - __bfloat162float(ah));
        float y0 = feats[2 * n], y1 = feats[2 * n + 1];
        float bb = fmaxf(y0 * w_seg1[cc] + y1 * w_seg1[C + cc] + b_seg1[cc], 0.f);
        __nv_bfloat16 bh = __float2bfloat16(bb);
        h2h[i] = bh;
        h2l[i] = __float2bfloat16(bb - __bfloat162float(bh));
    }
}

__global__ void ew_gnrelu_split(const float* __restrict__ T, const float* __restrict__ g,
                                const float* __restrict__ b,
                                __nv_bfloat16* __restrict__ Xhi,
                                __nv_bfloat16* __restrict__ Xlo)
{
    int n = blockIdx.x * 8 + (threadIdx.x >> 5);
    int lane = threadIdx.x & 31;
    if (n >= N_NODES) return;
    float4 v = *(const float4*)(T + (size_t)n * C + lane * 4);
    float s1 = v.x + v.y + v.z + v.w;
    float s2 = v.x * v.x + v.y * v.y + v.z * v.z + v.w * v.w;
    #pragma unroll
    for (int o = 16; o >= 1; o >>= 1) {
        s1 += __shfl_xor_sync(0xffffffffu, s1, o);
        s2 += __shfl_xor_sync(0xffffffffu, s2, o);
    }
    float mu = s1 * (1.f / 128.f);
    float var = s2 * (1.f / 128.f) - mu * mu;
    float sc = rsqrtf(var + 1e-5f);
    float4 gv = *(const float4*)(g + lane * 4);
    float4 bv = *(const float4*)(b + lane * 4);
    float v0 = fmaxf((v.x - mu) * sc * gv.x + bv.x, 0.f);
    float v1 = fmaxf((v.y - mu) * sc * gv.y + bv.y, 0.f);
    float v2 = fmaxf((v.z - mu) * sc * gv.z + bv.z, 0.f);
    float v3 = fmaxf((v.w - mu) * sc * gv.w + bv.w, 0.f);
    __nv_bfloat16 h0 = __float2bfloat16(v0), h1 = __float2bfloat16(v1);
    __nv_bfloat16 h2 = __float2bfloat16(v2), h3 = __float2bfloat16(v3);
    __nv_bfloat162 hh0; hh0.x = h0; hh0.y = h1;
    __nv_bfloat162 hh1; hh1.x = h2; hh1.y = h3;
    uint2 H; H.x = *(u32*)&hh0; H.y = *(u32*)&hh1;
    uint2 L;
    L.x = pack_bf2(v0 - __bfloat162float(h0), v1 - __bfloat162float(h1));
    L.y = pack_bf2(v2 - __bfloat162float(h2), v3 - __bfloat162float(h3));
    size_t off = (size_t)n * 32 + lane;
    ((uint2*)Xhi)[off] = H;
    ((uint2*)Xlo)[off] = L;
}

// ================= host launcher =================
extern "C" void kernel_launch(void* const* d_in, const int* in_sizes, int n_in,
                              void* d_out, int out_size)
{
    const float* control  = (const float*)d_in[0];
    const float* turn     = (const float*)d_in[1];
    const float* inter    = (const float*)d_in[2];
    const float* ctrs     = (const float*)d_in[3];
    const float* feats    = (const float*)d_in[4];
    const int*   pre      = (const int*)d_in[5];
    const int*   suc      = (const int*)d_in[6];
    const int*   left     = (const int*)d_in[7];
    const int*   right    = (const int*)d_in[8];
    const float* w_in1    = (const float*)d_in[9];
    const float* b_in1    = (const float*)d_in[10];
    const float* w_in2    = (const float*)d_in[11];
    const float* gn_in_g  = (const float*)d_in[12];
    const float* gn_in_b  = (const float*)d_in[13];
    const float* w_seg1   = (const float*)d_in[14];
    const float* b_seg1   = (const float*)d_in[15];
    const float* w_seg2   = (const float*)d_in[16];
    const float* gn_seg_g = (const float*)d_in[17];
    const float* gn_seg_b = (const float*)d_in[18];
    const float* w_meta   = (const float*)d_in[19];
    const float* gn_m_g   = (const float*)d_in[20];
    const float* gn_m_b   = (const float*)d_in[21];
    const float* ctr_w    = (const float*)d_in[22];
    const float* pre_w    = (const float*)d_in[23];
    const float* suc_w    = (const float*)d_in[24];
    const float* left_w   = (const float*)d_in[25];
    const float* right_w  = (const float*)d_in[26];
    const float* norm_g   = (const float*)d_in[27];
    const float* norm_b   = (const float*)d_in[28];
    const float* ctr2_w   = (const float*)d_in[29];
    const float* ctr2_g   = (const float*)d_in[30];
    const float* ctr2_b   = (const float*)d_in[31];

    float *F, *G, *T;
    __nv_bfloat16 *Fhi, *Flo, *Xhi, *Xlo, *Whi, *Wlo;
    cudaGetSymbolAddress((void**)&F, g_F);
    cudaGetSymbolAddress((void**)&G, g_G);
    cudaGetSymbolAddress((void**)&T, g_T);
    cudaGetSymbolAddress((void**)&Fhi, g_Fhi);
    cudaGetSymbolAddress((void**)&Flo, g_Flo);
    cudaGetSymbolAddress((void**)&Xhi, g_Xhi);
    cudaGetSymbolAddress((void**)&Xlo, g_Xlo);
    cudaGetSymbolAddress((void**)&Whi, g_Whi);
    cudaGetSymbolAddress((void**)&Wlo, g_Wlo);

    cudaFuncSetAttribute(hmma_gemm<0>, cudaFuncAttributeMaxDynamicSharedMemorySize, DSM);
    cudaFuncSetAttribute(hmma_gemm<2>, cudaFuncAttributeMaxDynamicSharedMemorySize, DSM);
    cudaFuncSetAttribute(hmma_gemm<3>, cudaFuncAttributeMaxDynamicSharedMemorySize, DSM);
    cudaFuncSetAttribute(hmma_gemm<4>, cudaFuncAttributeMaxDynamicSharedMemorySize, DSM);
    cudaFuncSetAttribute(edge_gemm, cudaFuncAttributeMaxDynamicSharedMemorySize, E_DSM);

    const int NB = (N_NODES + 127) / 128;
    const float* wext = w_meta + 128 * C;

    // 1: fused prep (ctrs tail copy + weight split + input branches)
    prep<<<PREP_COPY_B + PREP_W_B + PREP_IN_B, 256>>>(
        ctrs, feats, w_in1, b_in1, w_seg1, b_seg1,
        w_in2, w_seg2, w_meta, ctr_w, pre_w, suc_w, left_w, right_w, ctr2_w,
        Whi, Wlo, Xhi, Xlo, Fhi, Flo, (float*)d_out + (size_t)N_NODES * C);
    // 2: T = gn(H1 @ w_in2)
    hmma_gemm<4><<<NB, 256, DSM>>>(Xhi, Xlo, Whi + OFF_IN2, Wlo + OFF_IN2,
        T, gn_in_g, gn_in_b, nullptr, nullptr, nullptr, N_NODES,
        nullptr, nullptr, nullptr, nullptr);
    // 3: F = relu(gn(H2 @ w_seg2) + T) -> split Xhi/Xlo
    hmma_gemm<2><<<NB, 256, DSM>>>(Fhi, Flo, Whi + OFF_SEG2, Wlo + OFF_SEG2,
        F, gn_seg_g, gn_seg_b, T, Xhi, Xlo, N_NODES,
        nullptr, nullptr, nullptr, nullptr);
    // 4: F = relu(gn(feat @ w_meta + extras @ wext)) -> split Fhi/Flo
    hmma_gemm<3><<<NB, 256, DSM>>>(Xhi, Xlo, Whi + OFF_META, Wlo + OFF_META,
        F, gn_m_g, gn_m_b, nullptr, Fhi, Flo, N_NODES,
        turn, control, inter, wext);

    // ---- 4 fuse layers ----
    for (int i = 0; i < 4; i++) {
        float* Fi = (i & 1) ? G : F;
        float* Fo = (i == 3) ? (float*)d_out : ((i & 1) ? F : G);

        // T = Fi @ ctr_w[i]
        hmma_gemm<0><<<NB, 256, DSM>>>(
            Fhi, Flo, Whi + OFF_CTR + (size_t)i * CC, Wlo + OFF_CTR + (size_t)i * CC,
            T, nullptr, nullptr, nullptr, nullptr, nullptr, N_NODES,
            nullptr, nullptr, nullptr, nullptr);
        // pre (y=0..5) + suc (y=6..11), persistent-B multi-tile
        edge_gemm<<<dim3(49, 12), 256, E_DSM>>>(
            Fhi, Flo, Whi + OFF_PS + (size_t)i * 12 * CC, Wlo + OFF_PS + (size_t)i * 12 * CC,
            T, pre, suc, 6, 2LL * EP, (long long)EP, EP, 16);
        // left (y=0) + right (y=1)
        edge_gemm<<<dim3(98, 2), 256, E_DSM>>>(
            Fhi, Flo, Whi + OFF_LR + (size_t)i * 2 * CC, Wlo + OFF_LR + (size_t)i * 2 * CC,
            T, left, right, 1, 2LL * EL, (long long)EL, EL, 2);
        // X = relu(gn(T)) -> split
        ew_gnrelu_split<<<(N_NODES + 7) / 8, 256>>>(T, norm_g + (size_t)i * C,
                                                    norm_b + (size_t)i * C, Xhi, Xlo);
        // Fo = relu(gn(X @ ctr2_w[i]) + Fi) -> split Fhi/Flo
        hmma_gemm<2><<<NB, 256, DSM>>>(
            Xhi, Xlo, Whi + OFF_CTR2 + (size_t)i * CC, Wlo + OFF_CTR2 + (size_t)i * CC,
            Fo, ctr2_g + (size_t)i * C, ctr2_b + (size_t)i * C, Fi, Fhi, Flo, N_NODES,
            nullptr, nullptr, nullptr, nullptr);
    }
}